// round 8
// baseline (speedup 1.0000x reference)
#include <cuda_runtime.h>
#include <cstddef>

// Problem constants (fixed by the dataset)
#define BS    32
#define NFEAT 64
#define NN    512      // N (graph nodes / m dim)
#define JJ    4
#define NOUT  128
#define CDIM  (JJ * NFEAT)        // 256 channels
#define ROWF4 512                 // one W n-row = 2048 floats = 512 float4
#define NCHUNK 16                 // chunk-blocks per batch
#define NPERCHUNK (NN / NCHUNK)   // 32 n-rows per block

// Per-(b,chunk) partial sums of W over n. 32*16*2048 floats = 4 MB, L2-hot.
__device__ float g_Spart[BS * NCHUNK * 2048];
// Per-batch completion counters. atomicInc with wrap=NCHUNK-1 self-resets to 0
// after exactly NCHUNK increments -> deterministic across graph replays.
__device__ unsigned int g_cnt[BS];

// ---------------------------------------------------------------------------
// Single fused kernel. __launch_bounds__(512, 4) caps regs at 32 so the
// streaming phase keeps the proven 4-blocks/SM, 74.5%-DRAM shape; the
// epilogue path (1 block in 16) may spill, which is fine (L2-latency work).
//
// Stream phase (all 512 blocks): Spart[b,chunk,:] = sum of 32 n-rows of W.
// Epilogue phase (last block per batch, overlapped with later batches' stream):
//   Ssh[j][m]  = sum_c Spart[b][c][m*4+j]          (L2-hot)
//   Gsh[c]     = sum_m Ssh[j][m] * X[b][f][m]      (L2-hot X)
//   y[b][o]    = fc_w[o,:] . Gsh + 512*fc_b[o]
// ---------------------------------------------------------------------------
__global__ __launch_bounds__(512, 4) void fused_kernel(
    const float4* __restrict__ W4,
    const float* __restrict__ X,
    const float* __restrict__ fc_w,
    const float* __restrict__ fc_b,
    float* __restrict__ out)
{
    __shared__ float Ssh[JJ][NN];   // 8 KB
    __shared__ float Gsh[CDIM];     // 1 KB
    __shared__ int isLast;

    const int chunk = blockIdx.x;   // fast dim: a batch's 16 blocks are adjacent
    const int b     = blockIdx.y;
    const int t     = threadIdx.x;  // 0..511

    // ---- stream phase ----
    {
        const size_t row0 = ((size_t)b * NN + (size_t)chunk * NPERCHUNK) * ROWF4;
        const float4* __restrict__ base = W4 + row0;

        float4 acc = make_float4(0.f, 0.f, 0.f, 0.f);
#pragma unroll
        for (int i = 0; i < NPERCHUNK; ++i) {
            // streaming, evict-first: W is read exactly once and exceeds L2
            float4 v = __ldcs(&base[(size_t)i * ROWF4 + t]);
            acc.x += v.x; acc.y += v.y; acc.z += v.z; acc.w += v.w;
        }
        float4* out4 = reinterpret_cast<float4*>(g_Spart);
        out4[((size_t)b * NCHUNK + chunk) * ROWF4 + t] = acc;  // default: L2-hot
    }

    // ---- completion detection (threadFenceReduction pattern) ----
    __threadfence();
    if (t == 0) {
        unsigned old = atomicInc(&g_cnt[b], NCHUNK - 1);  // wraps to 0: self-reset
        isLast = (old == NCHUNK - 1);
    }
    __syncthreads();
    if (!isLast) return;

    // ================= epilogue for batch b (one block, 512 thr) =============
    const int w    = t >> 5;        // warp 0..15
    const int lane = t & 31;

    // phase 1: reduce 16 chunk partials -> Ssh[j][m] (coalesced, L2-hot)
    const float* __restrict__ part = g_Spart + (size_t)b * NCHUNK * 2048;
#pragma unroll 1
    for (int i = 0; i < 4; ++i) {
        const int slot = t + i * 512;            // 0..2047 = m*4+j
        float a = 0.f;
#pragma unroll
        for (int c = 0; c < NCHUNK; ++c) a += part[(size_t)c * 2048 + slot];
        Ssh[slot & 3][slot >> 2] = a;
    }
    __syncthreads();

    // phase 2: G. Each warp handles 4 f's (one per iteration, low reg pressure);
    // lanes stride m -> coalesced X reads (L2-hot).
    const float* __restrict__ Xb = X + (size_t)b * NFEAT * NN;
#pragma unroll 1
    for (int fi = 0; fi < 4; ++fi) {
        const int f = w * 4 + fi;                // 0..63
        float a0 = 0.f, a1 = 0.f, a2 = 0.f, a3 = 0.f;
#pragma unroll
        for (int i = 0; i < 16; ++i) {
            const int m = i * 32 + lane;
            const float xv = Xb[(size_t)f * NN + m];
            a0 += Ssh[0][m] * xv;
            a1 += Ssh[1][m] * xv;
            a2 += Ssh[2][m] * xv;
            a3 += Ssh[3][m] * xv;
        }
#pragma unroll
        for (int s = 16; s > 0; s >>= 1) {
            a0 += __shfl_xor_sync(0xffffffffu, a0, s);
            a1 += __shfl_xor_sync(0xffffffffu, a1, s);
            a2 += __shfl_xor_sync(0xffffffffu, a2, s);
            a3 += __shfl_xor_sync(0xffffffffu, a3, s);
        }
        if (lane == 0) {
            Gsh[0 * NFEAT + f] = a0;
            Gsh[1 * NFEAT + f] = a1;
            Gsh[2 * NFEAT + f] = a2;
            Gsh[3 * NFEAT + f] = a3;
        }
    }
    __syncthreads();

    // phase 3: y. Each warp handles 8 o's; lanes stride c (coalesced fc_w).
#pragma unroll 1
    for (int oi = 0; oi < 8; ++oi) {
        const int o = w * 8 + oi;                // 0..127
        const float* __restrict__ wrow = fc_w + (size_t)o * CDIM;
        float a = 0.f;
#pragma unroll
        for (int i = 0; i < 8; ++i) {
            const int c = i * 32 + lane;
            a += wrow[c] * Gsh[c];
        }
#pragma unroll
        for (int s = 16; s > 0; s >>= 1) a += __shfl_xor_sync(0xffffffffu, a, s);
        if (lane == 0) out[(size_t)b * NOUT + o] = a + (float)NN * fc_b[o];
    }
}

// ---------------------------------------------------------------------------
// Inputs (metadata order): X[32,64,512] f32, W[32,512,512,4] f32,
// fc_w[128,256] f32, fc_b[128] f32, N_batch (int), mask[32,512] f32 (unused).
// Output: y[32,128] f32.
// ---------------------------------------------------------------------------
extern "C" void kernel_launch(void* const* d_in, const int* in_sizes, int n_in,
                              void* d_out, int out_size)
{
    const float* X    = (const float*)d_in[0];
    const float* W    = (const float*)d_in[1];
    const float* fc_w = (const float*)d_in[2];
    const float* fc_b = (const float*)d_in[3];
    float*       out  = (float*)d_out;

    dim3 grid(NCHUNK, BS);   // chunk fast, batch slow -> early batches finish early
    fused_kernel<<<grid, 512>>>(reinterpret_cast<const float4*>(W),
                                X, fc_w, fc_b, out);
}

// round 9
// speedup vs baseline: 1.3537x; 1.3537x over previous
#include <cuda_runtime.h>
#include <cstddef>

// Problem constants (fixed by the dataset)
#define BS    32
#define NFEAT 64
#define NN    512      // N (graph nodes / m dim)
#define JJ    4
#define NOUT  128
#define CDIM  (JJ * NFEAT)        // 256 channels
#define ROWF4 512                 // one W n-row = 2048 floats = 512 float4
#define NCHUNK 16                 // chunk-blocks per batch in kernel 1
#define NPERCHUNK (NN / NCHUNK)   // 32 n-rows per block
#define EQ    8                   // epilogue blocks per batch

// Per-(b,chunk) partial sums of W over n. 32*16*2048 floats = 4 MB.
__device__ float g_Spart[BS * NCHUNK * 2048];
// Reduced, transposed S[b][j][m]. 256 KB.
__device__ float g_S[BS * JJ * NN];
// Per-batch completion counters; atomicInc wrap=EQ-1 self-resets every replay.
__device__ unsigned int g_cnt[BS];
// Sink for the fc_w prefetch discard-trick (never actually written).
__device__ float g_sink;

// ---------------------------------------------------------------------------
// Kernel 1 (the 134 MB HBM stream) — exact round-6 shape (regs=32, ~85% HBM).
// Spart[b,chunk,slot] = sum of 32 n-rows; 512 thr x float4 = one 8KB row/iter.
// ---------------------------------------------------------------------------
__global__ __launch_bounds__(512) void reduce_w_kernel(const float4* __restrict__ W4) {
    const int b     = blockIdx.y;
    const int chunk = blockIdx.x;
    const int t     = threadIdx.x;          // 0..511

    const size_t row0 = ((size_t)b * NN + (size_t)chunk * NPERCHUNK) * ROWF4;
    const float4* __restrict__ base = W4 + row0;

    float4 acc = make_float4(0.f, 0.f, 0.f, 0.f);
#pragma unroll
    for (int i = 0; i < NPERCHUNK; ++i) {
        // streaming, evict-first: W is read exactly once and exceeds L2
        float4 v = __ldcs(&base[(size_t)i * ROWF4 + t]);
        acc.x += v.x; acc.y += v.y; acc.z += v.z; acc.w += v.w;
    }
    float4* out4 = reinterpret_cast<float4*>(g_Spart);
    out4[((size_t)b * NCHUNK + chunk) * ROWF4 + t] = acc;
}

// ---------------------------------------------------------------------------
// Kernel 2 (epilogue), grid (BS, EQ) x 256 thr:
//  stage 1 (all 256 blocks): reduce a 256-slot slice of Spart -> S[b][j][m];
//                            prefetch fc_w slice into L2.
//  stage 2 (8th block/batch): Gsh[c] = sum_m S[b][j][m] * X[b][f][m]
//  stage 3 (same block):      y[b][o] = fc_w[o,:] . Gsh + 512*fc_b[o]
// ---------------------------------------------------------------------------
__global__ __launch_bounds__(256) void epilogue_kernel(
    const float* __restrict__ X,
    const float* __restrict__ fc_w,
    const float* __restrict__ fc_b,
    float* __restrict__ out)
{
    __shared__ float Ssh[JJ][NN];   // 8 KB
    __shared__ float Gsh[CDIM];     // 1 KB
    __shared__ int isLast;

    const int b = blockIdx.x;
    const int q = blockIdx.y;       // 0..7
    const int t = threadIdx.x;      // 0..255

    // ---- stage 1: reduce slots [q*256, q*256+256) over 16 chunks ----
    {
        const float* __restrict__ part = g_Spart + (size_t)b * NCHUNK * 2048;
        const int slot = q * 256 + t;            // slot = m*4+j
        float a = 0.f;
#pragma unroll
        for (int c = 0; c < NCHUNK; ++c) a += part[(size_t)c * 2048 + slot];
        g_S[((size_t)b * JJ + (slot & 3)) * NN + (slot >> 2)] = a;
    }

    // ---- warm fc_w into L2 (discard trick; branch can never be taken) ----
    {
        const float4* __restrict__ w4 = reinterpret_cast<const float4*>(fc_w);
        float s = 0.f;
#pragma unroll
        for (int i = 0; i < 4; ++i) {
            const float4 v = __ldg(&w4[q * 1024 + i * 256 + t]);  // 8192 f4 total / 8 q
            s += v.x + v.y + v.z + v.w;
        }
        if (s == -1.2345678e33f) g_sink = s;
    }

    __threadfence();
    if (t == 0) {
        unsigned old = atomicInc(&g_cnt[b], EQ - 1);  // wraps to 0: self-resets
        isLast = (old == EQ - 1);
    }
    __syncthreads();
    if (!isLast) return;

    // ---- stage 2: load S to shared, compute G ----
    {
        const float4* __restrict__ S4 = reinterpret_cast<const float4*>(g_S + (size_t)b * JJ * NN);
        float4* __restrict__ Ssh4 = reinterpret_cast<float4*>(&Ssh[0][0]);
#pragma unroll
        for (int i = 0; i < 2; ++i) Ssh4[t + i * 256] = S4[t + i * 256];
    }
    __syncthreads();

    const int w    = t >> 5;        // warp 0..7
    const int lane = t & 31;
    const float* __restrict__ Xb = X + (size_t)b * NFEAT * NN;

#pragma unroll 1
    for (int fp = 0; fp < 4; ++fp) {
        const int f0 = w * 8 + fp * 2;
        const int f1 = f0 + 1;
        float a00 = 0.f, a01 = 0.f, a02 = 0.f, a03 = 0.f;
        float a10 = 0.f, a11 = 0.f, a12 = 0.f, a13 = 0.f;
#pragma unroll
        for (int i = 0; i < 16; ++i) {
            const int m = i * 32 + lane;
            const float x0 = Xb[(size_t)f0 * NN + m];
            const float x1 = Xb[(size_t)f1 * NN + m];
            const float s0 = Ssh[0][m], s1 = Ssh[1][m], s2 = Ssh[2][m], s3 = Ssh[3][m];
            a00 += s0 * x0; a01 += s1 * x0; a02 += s2 * x0; a03 += s3 * x0;
            a10 += s0 * x1; a11 += s1 * x1; a12 += s2 * x1; a13 += s3 * x1;
        }
#pragma unroll
        for (int s = 16; s > 0; s >>= 1) {
            a00 += __shfl_xor_sync(0xffffffffu, a00, s);
            a01 += __shfl_xor_sync(0xffffffffu, a01, s);
            a02 += __shfl_xor_sync(0xffffffffu, a02, s);
            a03 += __shfl_xor_sync(0xffffffffu, a03, s);
            a10 += __shfl_xor_sync(0xffffffffu, a10, s);
            a11 += __shfl_xor_sync(0xffffffffu, a11, s);
            a12 += __shfl_xor_sync(0xffffffffu, a12, s);
            a13 += __shfl_xor_sync(0xffffffffu, a13, s);
        }
        if (lane == 0) {
            Gsh[0 * NFEAT + f0] = a00; Gsh[1 * NFEAT + f0] = a01;
            Gsh[2 * NFEAT + f0] = a02; Gsh[3 * NFEAT + f0] = a03;
            Gsh[0 * NFEAT + f1] = a10; Gsh[1 * NFEAT + f1] = a11;
            Gsh[2 * NFEAT + f1] = a12; Gsh[3 * NFEAT + f1] = a13;
        }
    }
    __syncthreads();

    // ---- stage 3: y. Warp w handles o in [w*16, w*16+16); float4 rows. ----
    const float4* __restrict__ Gsh4 = reinterpret_cast<const float4*>(Gsh);
#pragma unroll 2
    for (int oi = 0; oi < 16; ++oi) {
        const int o = w * 16 + oi;               // 0..127
        const float4* __restrict__ wrow4 = reinterpret_cast<const float4*>(fc_w + (size_t)o * CDIM);
        float a = 0.f;
#pragma unroll
        for (int i = 0; i < 2; ++i) {
            const int q4 = i * 32 + lane;        // 0..63 float4 slots
            const float4 wv = wrow4[q4];
            const float4 gv = Gsh4[q4];
            a += wv.x * gv.x + wv.y * gv.y + wv.z * gv.z + wv.w * gv.w;
        }
#pragma unroll
        for (int s = 16; s > 0; s >>= 1) a += __shfl_xor_sync(0xffffffffu, a, s);
        if (lane == 0) out[(size_t)b * NOUT + o] = a + (float)NN * fc_b[o];
    }
}

// ---------------------------------------------------------------------------
// Inputs (metadata order): X[32,64,512] f32, W[32,512,512,4] f32,
// fc_w[128,256] f32, fc_b[128] f32, N_batch (int), mask[32,512] f32 (unused).
// Output: y[32,128] f32.
// ---------------------------------------------------------------------------
extern "C" void kernel_launch(void* const* d_in, const int* in_sizes, int n_in,
                              void* d_out, int out_size)
{
    const float* X    = (const float*)d_in[0];
    const float* W    = (const float*)d_in[1];
    const float* fc_w = (const float*)d_in[2];
    const float* fc_b = (const float*)d_in[3];
    float*       out  = (float*)d_out;

    dim3 grid1(NCHUNK, BS);
    reduce_w_kernel<<<grid1, 512>>>(reinterpret_cast<const float4*>(W));
    dim3 grid2(BS, EQ);
    epilogue_kernel<<<grid2, 256>>>(X, fc_w, fc_b, out);
}

// round 10
// speedup vs baseline: 1.6025x; 1.1838x over previous
#include <cuda_runtime.h>
#include <cstddef>

// Problem constants (fixed by the dataset)
#define BS    32
#define NFEAT 64
#define NN    512      // N (graph nodes / m dim)
#define JJ    4
#define NOUT  128
#define CDIM  (JJ * NFEAT)        // 256 channels
#define ROWF4 512                 // one W n-row = 2048 floats = 512 float4
#define NCHUNK 16                 // chunk-blocks per batch in kernel 1
#define NPERCHUNK (NN / NCHUNK)   // 32 n-rows per block
#define MQ    4                   // m-groups per batch in epilogue
#define MTL   (NN / MQ)           // 128 m per group

// Per-(b,chunk) partial sums of W over n. 32*16*2048 floats = 4 MB.
__device__ float g_Spart[BS * NCHUNK * 2048];
// Partial G per (b, m-group): 32*4*256 floats = 128 KB.
__device__ float g_Gpart[BS * MQ * CDIM];
// Per-batch completion counters; atomicInc wrap=MQ-1 self-resets every replay.
__device__ unsigned int g_cnt[BS];

// ---------------------------------------------------------------------------
// Kernel 1 (the 134 MB HBM stream) — proven round-6 shape, untouched.
// Spart[b,chunk,slot] = sum of 32 n-rows; 512 thr x float4 = one 8KB row/iter.
// ---------------------------------------------------------------------------
__global__ __launch_bounds__(512) void reduce_w_kernel(const float4* __restrict__ W4) {
    const int chunk = blockIdx.x;
    const int b     = blockIdx.y;
    const int t     = threadIdx.x;          // 0..511

    const size_t row0 = ((size_t)b * NN + (size_t)chunk * NPERCHUNK) * ROWF4;
    const float4* __restrict__ base = W4 + row0;

    float4 acc = make_float4(0.f, 0.f, 0.f, 0.f);
#pragma unroll
    for (int i = 0; i < NPERCHUNK; ++i) {
        // streaming, evict-first: W is read exactly once and exceeds L2
        float4 v = __ldcs(&base[(size_t)i * ROWF4 + t]);
        acc.x += v.x; acc.y += v.y; acc.z += v.z; acc.w += v.w;
    }
    float4* out4 = reinterpret_cast<float4*>(g_Spart);
    out4[((size_t)b * NCHUNK + chunk) * ROWF4 + t] = acc;
}

// ---------------------------------------------------------------------------
// Kernel 2 (epilogue), grid (BS, MQ) x 256 thr. Block (b,q) owns m-range
// [q*128, q*128+128):
//  A: Ssh[j][mloc] = sum_c Spart[b][c][q*512 + mloc*4+j]      (coalesced)
//  B: Xs[f][mloc]  = X[b][f][q*128+mloc]                      (coalesced f4)
//  C: Gpart[b][q][c] = sum_mloc Ssh[j][mloc] * Xs[f][mloc]    (shared only)
//  D (last block per batch): Gsh = sum_q Gpart; y[b][o] = fc_w[o,:].Gsh + 512*fc_b[o]
// ---------------------------------------------------------------------------
__global__ __launch_bounds__(256) void epilogue_kernel(
    const float* __restrict__ X,
    const float* __restrict__ fc_w,
    const float* __restrict__ fc_b,
    float* __restrict__ out)
{
    __shared__ float Ssh[JJ][MTL];       // 2 KB
    __shared__ float Xs[NFEAT][MTL + 1]; // 33 KB, stride 129 -> conflict-free
    __shared__ float Gsh[CDIM];          // 1 KB
    __shared__ int isLast;

    const int b = blockIdx.x;
    const int q = blockIdx.y;       // 0..3
    const int t = threadIdx.x;      // 0..255

    // ---- A: reduce Spart slots [q*512, q*512+512) over 16 chunks ----
    const float* __restrict__ part = g_Spart + (size_t)b * NCHUNK * 2048 + q * 512;
#pragma unroll
    for (int i = 0; i < 2; ++i) {
        const int sl = t + i * 256;              // local slot 0..511 = mloc*4+j
        float a = 0.f;
#pragma unroll
        for (int c = 0; c < NCHUNK; ++c) a += part[(size_t)c * 2048 + sl];
        Ssh[sl & 3][sl >> 2] = a;
    }

    // ---- B: stage X tile [64][128] (float4, coalesced) ----
    const float4* __restrict__ Xb4 =
        reinterpret_cast<const float4*>(X + (size_t)b * NFEAT * NN);
#pragma unroll
    for (int i = 0; i < 8; ++i) {
        const int idx = t + i * 256;             // 0..2047 f4 slots
        const int f   = idx >> 5;                // 32 f4 per row-tile
        const int mq4 = idx & 31;
        const float4 v = Xb4[(size_t)f * (NN / 4) + q * (MTL / 4) + mq4];
        Xs[f][mq4 * 4 + 0] = v.x;
        Xs[f][mq4 * 4 + 1] = v.y;
        Xs[f][mq4 * 4 + 2] = v.z;
        Xs[f][mq4 * 4 + 3] = v.w;
    }
    __syncthreads();

    // ---- C: partial G for all 256 channels, from shared only ----
    {
        const int j = t >> 6;      // uniform per warp -> Ssh broadcast
        const int f = t & 63;
        float g = 0.f;
#pragma unroll 16
        for (int mm = 0; mm < MTL; ++mm) g += Ssh[j][mm] * Xs[f][mm];
        g_Gpart[((size_t)b * MQ + q) * CDIM + t] = g;
    }

    // ---- gate: last block of batch b proceeds to D ----
    __threadfence();
    if (t == 0) {
        unsigned old = atomicInc(&g_cnt[b], MQ - 1);  // wraps to 0: self-resets
        isLast = (old == MQ - 1);
    }
    __syncthreads();
    if (!isLast) return;

    // ---- D: sum the 4 partials, then y ----
    {
        const float* __restrict__ gp = g_Gpart + (size_t)b * MQ * CDIM;
        Gsh[t] = gp[0 * CDIM + t] + gp[1 * CDIM + t] + gp[2 * CDIM + t] + gp[3 * CDIM + t];
    }
    __syncthreads();

    const int w    = t >> 5;        // warp 0..7
    const int lane = t & 31;
    const float4* __restrict__ Gsh4 = reinterpret_cast<const float4*>(Gsh);
#pragma unroll 2
    for (int oi = 0; oi < 16; ++oi) {
        const int o = w * 16 + oi;               // 0..127
        const float4* __restrict__ wrow4 =
            reinterpret_cast<const float4*>(fc_w + (size_t)o * CDIM);
        float a = 0.f;
#pragma unroll
        for (int i = 0; i < 2; ++i) {
            const int q4 = i * 32 + lane;        // 0..63 float4 slots
            const float4 wv = wrow4[q4];
            const float4 gv = Gsh4[q4];
            a += wv.x * gv.x + wv.y * gv.y + wv.z * gv.z + wv.w * gv.w;
        }
#pragma unroll
        for (int s = 16; s > 0; s >>= 1) a += __shfl_xor_sync(0xffffffffu, a, s);
        if (lane == 0) out[(size_t)b * NOUT + o] = a + (float)NN * fc_b[o];
    }
}

// ---------------------------------------------------------------------------
// Inputs (metadata order): X[32,64,512] f32, W[32,512,512,4] f32,
// fc_w[128,256] f32, fc_b[128] f32, N_batch (int), mask[32,512] f32 (unused).
// Output: y[32,128] f32.
// ---------------------------------------------------------------------------
extern "C" void kernel_launch(void* const* d_in, const int* in_sizes, int n_in,
                              void* d_out, int out_size)
{
    const float* X    = (const float*)d_in[0];
    const float* W    = (const float*)d_in[1];
    const float* fc_w = (const float*)d_in[2];
    const float* fc_b = (const float*)d_in[3];
    float*       out  = (float*)d_out;

    dim3 grid1(NCHUNK, BS);   // chunk fast, batch slow
    reduce_w_kernel<<<grid1, 512>>>(reinterpret_cast<const float4*>(W));
    dim3 grid2(BS, MQ);
    epilogue_kernel<<<grid2, 256>>>(X, fc_w, fc_b, out);
}

// round 11
// speedup vs baseline: 1.6501x; 1.0297x over previous
#include <cuda_runtime.h>
#include <cstddef>

// Problem constants (fixed by the dataset)
#define BS    32
#define NFEAT 64
#define NN    512      // N (graph nodes / m dim)
#define JJ    4
#define NOUT  128
#define CDIM  (JJ * NFEAT)        // 256 channels
#define ROWF4 512                 // one W n-row = 2048 floats = 512 float4
#define NCHUNK 16                 // chunk-blocks per batch in kernel 1
#define NPERCHUNK (NN / NCHUNK)   // 32 n-rows per block
#define EQ    8                   // epilogue m-groups per batch
#define MTL   (NN / EQ)           // 64 m per group

// Per-(b,chunk) partial sums of W over n. 32*16*2048 floats = 4 MB.
__device__ float g_Spart[BS * NCHUNK * 2048];
// Partial G per (b, m-group): 32*8*256 floats = 256 KB.
__device__ float g_Gpart[BS * EQ * CDIM];
// Per-batch completion counters; atomicInc wrap=EQ-1 self-resets every replay.
__device__ unsigned int g_cnt[BS];

// ---------------------------------------------------------------------------
// Kernel 1 (the 134 MB HBM stream) — proven shape, untouched.
// Spart[b,chunk,slot] = sum of 32 n-rows; 512 thr x float4 = one 8KB row/iter.
// ---------------------------------------------------------------------------
__global__ __launch_bounds__(512) void reduce_w_kernel(const float4* __restrict__ W4) {
    const int chunk = blockIdx.x;
    const int b     = blockIdx.y;
    const int t     = threadIdx.x;          // 0..511

    const size_t row0 = ((size_t)b * NN + (size_t)chunk * NPERCHUNK) * ROWF4;
    const float4* __restrict__ base = W4 + row0;

    float4 acc = make_float4(0.f, 0.f, 0.f, 0.f);
#pragma unroll
    for (int i = 0; i < NPERCHUNK; ++i) {
        // streaming, evict-first: W is read exactly once and exceeds L2
        float4 v = __ldcs(&base[(size_t)i * ROWF4 + t]);
        acc.x += v.x; acc.y += v.y; acc.z += v.z; acc.w += v.w;
    }
    float4* out4 = reinterpret_cast<float4*>(g_Spart);
    out4[((size_t)b * NCHUNK + chunk) * ROWF4 + t] = acc;
}

// ---------------------------------------------------------------------------
// Kernel 2 (epilogue, PDL secondary). grid (BS, EQ) x 256 thr. Block (b,q)
// owns m-range [q*64, q*64+64):
//  pre-sync:  Xs[f][mloc] = X[b][f][q*64+mloc]        (independent of K1!)
//  -- cudaGridDependencySynchronize() --
//  A: Ssh[j][mloc] = sum_c Spart[b][c][ (q*64+mloc)*4+j ]  (float4, 4-way split)
//  C: Gpart[b][q][c] = sum_mloc Ssh[j][mloc] * Xs[f][mloc] (shared only)
//  D (last block per batch): Gsh = sum_q Gpart; y = fc_w . Gsh + 512*fc_b
// ---------------------------------------------------------------------------
__global__ __launch_bounds__(256) void epilogue_kernel(
    const float* __restrict__ X,
    const float* __restrict__ fc_w,
    const float* __restrict__ fc_b,
    float* __restrict__ out)
{
    __shared__ float  Xs[NFEAT][MTL + 1]; // 16.6 KB, odd stride -> conflict-free
    __shared__ float4 red[256];           // 4 KB chunk-split partials
    __shared__ float  Ssh[JJ][MTL];       // 1 KB
    __shared__ float  Gsh[CDIM];          // 1 KB
    __shared__ int isLast;

    const int b = blockIdx.x;
    const int q = blockIdx.y;       // 0..7
    const int t = threadIdx.x;      // 0..255

    // ---- pre-sync: stage X tile [64][64] (float4, coalesced). X does not
    // depend on kernel 1, so this overlaps kernel 1's tail under PDL. ----
    const float4* __restrict__ Xb4 =
        reinterpret_cast<const float4*>(X + (size_t)b * NFEAT * NN);
#pragma unroll
    for (int i = 0; i < 4; ++i) {
        const int idx = t + i * 256;             // 0..1023 f4 slots
        const int f   = idx >> 4;                // 16 f4 per f-row
        const int mq4 = idx & 15;
        const float4 v = Xb4[(size_t)f * (NN / 4) + q * (MTL / 4) + mq4];
        Xs[f][mq4 * 4 + 0] = v.x;
        Xs[f][mq4 * 4 + 1] = v.y;
        Xs[f][mq4 * 4 + 2] = v.z;
        Xs[f][mq4 * 4 + 3] = v.w;
    }

    // wait for kernel 1's Spart to be globally visible
    cudaGridDependencySynchronize();

    // ---- A: reduce chunk partials for f4-slots [q*64, q*64+64). Thread t
    // covers slot (t&63) for chunks [cgrp*4, cgrp*4+4), cgrp = t>>6. ----
    {
        const int sl4  = q * MTL + (t & 63);     // global f4 slot = m index
        const int cgrp = t >> 6;                 // 0..3
        const float4* __restrict__ part4 =
            reinterpret_cast<const float4*>(g_Spart) + (size_t)b * NCHUNK * 512 + sl4;
        float4 a = make_float4(0.f, 0.f, 0.f, 0.f);
#pragma unroll
        for (int k = 0; k < 4; ++k) {
            const float4 v = part4[(size_t)(cgrp * 4 + k) * 512];
            a.x += v.x; a.y += v.y; a.z += v.z; a.w += v.w;
        }
        red[t] = a;
    }
    __syncthreads();
    if (t < MTL) {
        float4 a = red[t];
        const float4 b1 = red[t + 64], b2 = red[t + 128], b3 = red[t + 192];
        a.x += b1.x + b2.x + b3.x;
        a.y += b1.y + b2.y + b3.y;
        a.z += b1.z + b2.z + b3.z;
        a.w += b1.w + b2.w + b3.w;
        Ssh[0][t] = a.x; Ssh[1][t] = a.y; Ssh[2][t] = a.z; Ssh[3][t] = a.w;
    }
    __syncthreads();

    // ---- C: partial G for all 256 channels, from shared only ----
    {
        const int j = t >> 6;      // uniform per warp -> Ssh broadcast
        const int f = t & 63;
        float g = 0.f;
#pragma unroll
        for (int mm = 0; mm < MTL; ++mm) g += Ssh[j][mm] * Xs[f][mm];
        g_Gpart[((size_t)b * EQ + q) * CDIM + t] = g;
    }

    // ---- gate: last block of batch b proceeds to D ----
    __threadfence();
    if (t == 0) {
        unsigned old = atomicInc(&g_cnt[b], EQ - 1);  // wraps to 0: self-resets
        isLast = (old == EQ - 1);
    }
    __syncthreads();
    if (!isLast) return;

    // ---- D: sum the 8 partials, then y ----
    {
        const float* __restrict__ gp = g_Gpart + (size_t)b * EQ * CDIM;
        float a = 0.f;
#pragma unroll
        for (int qq = 0; qq < EQ; ++qq) a += gp[(size_t)qq * CDIM + t];
        Gsh[t] = a;
    }
    __syncthreads();

    const int w    = t >> 5;        // warp 0..7
    const int lane = t & 31;
    const float4* __restrict__ Gsh4 = reinterpret_cast<const float4*>(Gsh);
#pragma unroll 2
    for (int oi = 0; oi < 16; ++oi) {
        const int o = w * 16 + oi;               // 0..127
        const float4* __restrict__ wrow4 =
            reinterpret_cast<const float4*>(fc_w + (size_t)o * CDIM);
        float a = 0.f;
#pragma unroll
        for (int i = 0; i < 2; ++i) {
            const int q4 = i * 32 + lane;        // 0..63 float4 slots
            const float4 wv = wrow4[q4];
            const float4 gv = Gsh4[q4];
            a += wv.x * gv.x + wv.y * gv.y + wv.z * gv.z + wv.w * gv.w;
        }
#pragma unroll
        for (int s = 16; s > 0; s >>= 1) a += __shfl_xor_sync(0xffffffffu, a, s);
        if (lane == 0) out[(size_t)b * NOUT + o] = a + (float)NN * fc_b[o];
    }
}

// ---------------------------------------------------------------------------
// Inputs (metadata order): X[32,64,512] f32, W[32,512,512,4] f32,
// fc_w[128,256] f32, fc_b[128] f32, N_batch (int), mask[32,512] f32 (unused).
// Output: y[32,128] f32.
// ---------------------------------------------------------------------------
extern "C" void kernel_launch(void* const* d_in, const int* in_sizes, int n_in,
                              void* d_out, int out_size)
{
    const float* X    = (const float*)d_in[0];
    const float* W    = (const float*)d_in[1];
    const float* fc_w = (const float*)d_in[2];
    const float* fc_b = (const float*)d_in[3];
    float*       out  = (float*)d_out;

    dim3 grid1(NCHUNK, BS);   // chunk fast, batch slow
    reduce_w_kernel<<<grid1, 512>>>(reinterpret_cast<const float4*>(W));

    // Epilogue as a PDL secondary: its blocks may launch on SMs freed during
    // kernel 1's tail wave; X staging runs pre-sync, Spart reads post-sync.
    cudaLaunchConfig_t cfg = {};
    cfg.gridDim  = dim3(BS, EQ);
    cfg.blockDim = dim3(256, 1, 1);
    cfg.dynamicSmemBytes = 0;
    cudaLaunchAttribute attrs[1];
    attrs[0].id = cudaLaunchAttributeProgrammaticStreamSerialization;
    attrs[0].val.programmaticStreamSerializationAllowed = 1;
    cfg.attrs = attrs;
    cfg.numAttrs = 1;
    cudaLaunchKernelEx(&cfg, epilogue_kernel, X, fc_w, fc_b, out);
}